// round 2
// baseline (speedup 1.0000x reference)
#include <cuda_runtime.h>
#include <cstdint>

#define BB 32
#define LL 2048
#define HH 512
#define CC 50
#define MM (BB * LL)   // 65536

// ---- scratch (static device globals; allocation-free) ----
__device__ float g_P1[(size_t)MM * HH];   // tanh(X W1^T)            128 MB
__device__ float g_P12[(size_t)MM * HH];  // P1 + tanh(P1 W2^T)      128 MB
__device__ float g_P3[(size_t)MM * CC];   // P12 W3^T                 13 MB

// sent_lens may be int32 or int64 (jax x64 flag dependent). lens in [1, 2048],
// so for int64 LE the high word of element 0 is 0; for int32, word[1] = len[1] >= 1.
__device__ __forceinline__ int load_len(const void* p, int b) {
    const int* w = (const int*)p;
    bool is64 = (w[1] == 0);
    return is64 ? w[2 * b] : w[b];
}

// ============================================================================
// GEMM 512x512: Out = f(A * W^T), A: (M,512) row-major, W: (512,512) row-major.
// MODE 0: Out=g_P1=tanh(acc), A from param.  MODE 1: A=g_P1, Out=g_P12=A+tanh(acc).
// Tiles: 128x128x8, 256 threads, warp-tiled 8x8 microtiles.
// ============================================================================
template <int MODE>
__global__ __launch_bounds__(256, 2) void sgemm_tanh(const float* __restrict__ Aparam,
                                                     const float* __restrict__ W) {
    constexpr int K = HH;
    const float* A = (MODE == 0) ? Aparam : g_P1;
    float* Out = (MODE == 0) ? g_P1 : g_P12;

    __shared__ float As[8][128];
    __shared__ float Bs[8][128];

    const int tid = threadIdx.x;
    const int row0 = blockIdx.x * 128;
    const int col0 = blockIdx.y * 128;

    const int ldr = tid >> 1;          // 0..127
    const int ldc = (tid & 1) * 4;     // 0 or 4

    const int warp = tid >> 5;
    const int lane = tid & 31;
    const int tm = (warp & 3) * 32 + (lane >> 3) * 8;  // m offset in tile
    const int tn = (warp >> 2) * 64 + (lane & 7) * 8;  // n offset in tile

    float acc[8][8] = {};

    const float* Ab = A + (size_t)(row0 + ldr) * K + ldc;
    const float* Wb = W + (size_t)(col0 + ldr) * K + ldc;

    for (int k0 = 0; k0 < K; k0 += 8) {
        float4 av = *(const float4*)(Ab + k0);
        float4 bv = *(const float4*)(Wb + k0);
        As[ldc + 0][ldr] = av.x; As[ldc + 1][ldr] = av.y;
        As[ldc + 2][ldr] = av.z; As[ldc + 3][ldr] = av.w;
        Bs[ldc + 0][ldr] = bv.x; Bs[ldc + 1][ldr] = bv.y;
        Bs[ldc + 2][ldr] = bv.z; Bs[ldc + 3][ldr] = bv.w;
        __syncthreads();
#pragma unroll
        for (int kk = 0; kk < 8; kk++) {
            float ar[8], br[8];
#pragma unroll
            for (int i = 0; i < 8; i++) ar[i] = As[kk][tm + i];
#pragma unroll
            for (int j = 0; j < 8; j++) br[j] = Bs[kk][tn + j];
#pragma unroll
            for (int i = 0; i < 8; i++)
#pragma unroll
                for (int j = 0; j < 8; j++) acc[i][j] += ar[i] * br[j];
        }
        __syncthreads();
    }

#pragma unroll
    for (int i = 0; i < 8; i++) {
        size_t m = (size_t)(row0 + tm + i);
        float o[8];
#pragma unroll
        for (int j = 0; j < 8; j++) {
            float v = tanhf(acc[i][j]);
            if (MODE == 1) v += A[m * K + col0 + tn + j];
            o[j] = v;
        }
        *(float4*)(Out + m * K + col0 + tn)     = make_float4(o[0], o[1], o[2], o[3]);
        *(float4*)(Out + m * K + col0 + tn + 4) = make_float4(o[4], o[5], o[6], o[7]);
    }
}

// ============================================================================
// GEMM3: g_P3 (M x 50) = g_P12 (M x 512) * W3^T (50 x 512)
// Tiles: 128 x 64(padded from 50) x 16, 256 threads, 8x4 microtiles.
// ============================================================================
__global__ __launch_bounds__(256) void gemm3_kernel(const float* __restrict__ W3) {
    __shared__ float As[16][128];
    __shared__ float Bs[16][64];

    const int tid = threadIdx.x;
    const int row0 = blockIdx.x * 128;

    const int ar_ = tid >> 1;          // 0..127
    const int ac_ = (tid & 1) * 8;     // 0 or 8
    const int br_ = tid >> 2;          // 0..63
    const int bc_ = (tid & 3) * 4;     // 0,4,8,12

    const int warp = tid >> 5;
    const int lane = tid & 31;
    const int tm = (warp & 3) * 32 + (lane >> 3) * 8;  // m offset
    const int tn = (warp >> 2) * 32 + (lane & 7) * 4;  // n offset (0..60)

    float acc[8][4] = {};

    for (int k0 = 0; k0 < HH; k0 += 16) {
        const float* ap = g_P12 + (size_t)(row0 + ar_) * HH + k0 + ac_;
        float4 a0 = *(const float4*)(ap);
        float4 a1 = *(const float4*)(ap + 4);
        As[ac_ + 0][ar_] = a0.x; As[ac_ + 1][ar_] = a0.y;
        As[ac_ + 2][ar_] = a0.z; As[ac_ + 3][ar_] = a0.w;
        As[ac_ + 4][ar_] = a1.x; As[ac_ + 5][ar_] = a1.y;
        As[ac_ + 6][ar_] = a1.z; As[ac_ + 7][ar_] = a1.w;
        float4 bvv = make_float4(0.f, 0.f, 0.f, 0.f);
        if (br_ < CC) bvv = *(const float4*)(W3 + (size_t)br_ * HH + k0 + bc_);
        Bs[bc_ + 0][br_] = bvv.x; Bs[bc_ + 1][br_] = bvv.y;
        Bs[bc_ + 2][br_] = bvv.z; Bs[bc_ + 3][br_] = bvv.w;
        __syncthreads();
#pragma unroll
        for (int kk = 0; kk < 16; kk++) {
            float ar[8], br[4];
#pragma unroll
            for (int i = 0; i < 8; i++) ar[i] = As[kk][tm + i];
#pragma unroll
            for (int j = 0; j < 4; j++) br[j] = Bs[kk][tn + j];
#pragma unroll
            for (int i = 0; i < 8; i++)
#pragma unroll
                for (int j = 0; j < 4; j++) acc[i][j] += ar[i] * br[j];
        }
        __syncthreads();
    }

#pragma unroll
    for (int i = 0; i < 8; i++) {
#pragma unroll
        for (int j = 0; j < 4; j++) {
            int n = tn + j;
            if (n < CC) g_P3[(size_t)(row0 + tm + i) * CC + n] = acc[i][j];
        }
    }
}

// ============================================================================
// Fill-at-(len-1) + avgpool3 (count_include_pad=False) + softmax + mask.
// One thread per (b, l). Block = 128 l's, smem holds 130 rows (halo of 1).
// ============================================================================
__global__ __launch_bounds__(128) void pool_softmax_kernel(const void* __restrict__ lens_raw,
                                                           float* __restrict__ attn,
                                                           float* __restrict__ smooth) {
    const int b = blockIdx.y;
    const int l0 = blockIdx.x * 128;
    const int len = load_len(lens_raw, b);

    __shared__ float s[130][CC];
    const int tid = threadIdx.x;

    for (int i = tid; i < 130 * CC; i += 128) {
        int rr = i / CC, c = i - rr * CC;
        int l = l0 - 1 + rr;
        l = max(0, min(l, LL - 1));       // edge rows clamped (unused at true edges)
        int src = min(l, len - 1);        // fill: positions >= len take row len-1
        s[rr][c] = g_P3[((size_t)b * LL + src) * CC + c];
    }
    __syncthreads();

    const int l = l0 + tid;
    const bool hasL = (l > 0), hasR = (l < LL - 1);
    const float inv = 1.0f / (float)(1 + (hasL ? 1 : 0) + (hasR ? 1 : 0));
    const int rr = tid + 1;

    float v[CC];
    float mx = -1e30f;
#pragma unroll
    for (int c = 0; c < CC; c++) {
        float t = s[rr][c];
        if (hasL) t += s[rr - 1][c];
        if (hasR) t += s[rr + 1][c];
        t *= inv;
        v[c] = t;
        mx = fmaxf(mx, t);
    }
    const size_t base = ((size_t)b * LL + l) * CC;
    float sum = 0.f;
#pragma unroll
    for (int c = 0; c < CC; c++) {
        smooth[base + c] = v[c];
        float e = expf(v[c] - mx);
        v[c] = e;
        sum += e;
    }
    const float isum = (l < len) ? (1.0f / sum) : 0.0f;
#pragma unroll
    for (int c = 0; c < CC; c++) attn[base + c] = v[c] * isum;
}

// ============================================================================
// class_inputs[b,c,h] = sum_l attn[b,l,c] * V[b,l,h]
// Per-CTA: one batch, 64 h-cols, Cpad=64 rows. 256 threads, 4x4 microtiles.
// ============================================================================
__global__ __launch_bounds__(256) void classmm_kernel(const float* __restrict__ attn,
                                                      const float* __restrict__ Vv,
                                                      float* __restrict__ Out) {
    const int b = blockIdx.y;
    const int h0 = blockIdx.x * 64;

    __shared__ float As[16][64];  // [l][c]
    __shared__ float Vs[16][64];  // [l][h]

    const int tid = threadIdx.x;
    const int tx = tid & 15;      // h group
    const int ty = tid >> 4;      // c group
    float acc[4][4] = {};

    for (int l0 = 0; l0 < LL; l0 += 16) {
        for (int i = tid; i < 16 * 64; i += 256) {
            int k = i >> 6, c = i & 63;
            As[k][c] = (c < CC) ? attn[((size_t)b * LL + l0 + k) * CC + c] : 0.f;
        }
        for (int i = tid; i < 16 * 64; i += 256) {
            int k = i >> 6, h = i & 63;
            Vs[k][h] = Vv[((size_t)b * LL + l0 + k) * HH + h0 + h];
        }
        __syncthreads();
#pragma unroll
        for (int k = 0; k < 16; k++) {
            float a_[4], v_[4];
#pragma unroll
            for (int i = 0; i < 4; i++) a_[i] = As[k][ty * 4 + i];
#pragma unroll
            for (int j = 0; j < 4; j++) v_[j] = Vs[k][tx * 4 + j];
#pragma unroll
            for (int i = 0; i < 4; i++)
#pragma unroll
                for (int j = 0; j < 4; j++) acc[i][j] += a_[i] * v_[j];
        }
        __syncthreads();
    }

#pragma unroll
    for (int i = 0; i < 4; i++) {
        int c = ty * 4 + i;
        if (c < CC) {
#pragma unroll
            for (int j = 0; j < 4; j++)
                Out[((size_t)b * CC + c) * HH + h0 + tx * 4 + j] = acc[i][j];
        }
    }
}

// ============================================================================
extern "C" void kernel_launch(void* const* d_in, const int* in_sizes, int n_in,
                              void* d_out, int out_size) {
    const float* keys = (const float*)d_in[0];
    const float* vals = (const float*)d_in[1];
    const void*  lens = d_in[2];
    const float* W1 = (const float*)d_in[3];
    const float* W2 = (const float*)d_in[4];
    const float* W3 = (const float*)d_in[5];

    float* attn   = (float*)d_out;                       // (B, L, C)
    float* cls    = attn + (size_t)BB * LL * CC;          // (B, C, H)
    float* smooth = cls + (size_t)BB * CC * HH;           // (B, L, C)

    dim3 g1(MM / 128, HH / 128);
    sgemm_tanh<0><<<g1, 256>>>(keys, W1);                 // g_P1 = tanh(X W1^T)
    sgemm_tanh<1><<<g1, 256>>>(keys, W2);                 // g_P12 = P1 + tanh(P1 W2^T)
    gemm3_kernel<<<MM / 128, 256>>>(W3);                  // g_P3 = P12 W3^T
    pool_softmax_kernel<<<dim3(LL / 128, BB), 128>>>(lens, attn, smooth);
    classmm_kernel<<<dim3(HH / 64, BB), 256>>>(attn, vals, cls);
}

// round 5
// speedup vs baseline: 1.2269x; 1.2269x over previous
#include <cuda_runtime.h>
#include <cstdint>
#include <math.h>

#define BB 32
#define LL 2048
#define HH 512
#define CC 50
#define MM (BB * LL)   // 65536

// ---- scratch (static device globals; allocation-free) ----
__device__ float g_P1h[(size_t)MM * HH];   // tf32-hi of tanh(X W1^T)
__device__ float g_P1l[(size_t)MM * HH];   // tf32-lo
__device__ float g_P12h[(size_t)MM * HH];  // tf32-hi of P1 + tanh(P1 W2^T)
__device__ float g_P12l[(size_t)MM * HH];  // tf32-lo
__device__ float g_P3[(size_t)MM * CC];    // P12 W3^T (fp32)

// ============================================================================
// helpers
// ============================================================================
__device__ __forceinline__ float tf32r(float x) {
    uint32_t u; asm("cvt.rna.tf32.f32 %0, %1;" : "=r"(u) : "f"(x));
    return __uint_as_float(u);
}
__device__ __forceinline__ void tsplit(float x, float& h, float& l) {
    h = tf32r(x);
    l = tf32r(x - h);
}

// d += a * b   (m16n8k8 tf32, row.col)
__device__ __forceinline__ void mma8(float* d, const uint32_t* a, const uint32_t* b) {
    asm volatile(
        "mma.sync.aligned.m16n8k8.row.col.f32.tf32.tf32.f32 "
        "{%0,%1,%2,%3},{%4,%5,%6,%7},{%8,%9},{%0,%1,%2,%3};"
        : "+f"(d[0]), "+f"(d[1]), "+f"(d[2]), "+f"(d[3])
        : "r"(a[0]), "r"(a[1]), "r"(a[2]), "r"(a[3]), "r"(b[0]), "r"(b[1]));
}

// sent_lens may be int32 or int64. lens in [1, 2048]: for int64 LE, word[1]=0.
__device__ __forceinline__ int load_len(const void* p, int b) {
    const int* w = (const int*)p;
    bool is64 = (w[1] == 0);
    return is64 ? w[2 * b] : w[b];
}

// ============================================================================
// tf32 3-term GEMM: D(128 x NT) = A(128 x 512) * W^T.
// MODE 0: A = keys (split on load), W = W1, epi: split(tanh(D)) -> g_P1h/l
// MODE 1: A = g_P1h/l,              W = W2, epi: split(P1 + tanh(D)) -> g_P12h/l
// MODE 2: A = g_P12h/l, NT=64,      W = W3 (50 rows), epi: D -> g_P3 (n<50)
//
// SMEM layout is fragment-ordered: per stage
//   Ah[mt][ks][lane][4], Al..., Bh[nt][ks][lane][2], Bl...
// so each lane's A frag = 1x LDS.128, B frag = 1x LDS.64.
// ============================================================================
template <int MODE>
__global__ __launch_bounds__(256, 1) void gemm_mma(const float* __restrict__ Ag,
                                                   const float* __restrict__ W) {
    constexpr int NT = (MODE == 2) ? 64 : 128;
    constexpr int KC = 16;
    constexpr int NCH = HH / KC;          // 32
    constexpr int A_ST = 128 * KC;        // 2048 floats per (hi|lo)
    constexpr int B_ST = NT * KC;
    constexpr int STAGE = 2 * A_ST + 2 * B_ST;
    constexpr int MI = (MODE == 2) ? 2 : 4;   // m-tiles (16 rows) per warp
    constexpr int ANUM = A_ST / 256;      // 8
    constexpr int BNUM = B_ST / 256;      // 8 or 4

    extern __shared__ __align__(16) float sm[];

    const int tid = threadIdx.x;
    const int lane = tid & 31;
    const int warp = tid >> 5;
    const int row0 = blockIdx.y * 128;
    const int col0 = blockIdx.x * NT;

    const int wm = (MODE == 2) ? (warp >> 1) : (warp >> 2);
    const int wn = (MODE == 2) ? (warp & 1) : (warp & 3);
    const int base_mt = wm * MI;          // first 16-row m-tile of this warp
    const int base_nt = wn * 4;           // first 8-col n-tile of this warp

    float acc[MI][4][4] = {};

    float a_h[ANUM], a_l[ANUM], b_h[BNUM], b_l[BNUM];

    auto g2r = [&](int ch) {
        const int k0 = ch * KC;
#pragma unroll
        for (int i = 0; i < ANUM; i++) {
            int flat = i * 256 + tid;
            int r = flat >> 4, kk = flat & 15;
            if (MODE == 0) {
                float x = Ag[(size_t)(row0 + r) * HH + k0 + kk];
                tsplit(x, a_h[i], a_l[i]);
            } else {
                const float* sh = (MODE == 1) ? g_P1h : g_P12h;
                const float* sl = (MODE == 1) ? g_P1l : g_P12l;
                size_t o = (size_t)(row0 + r) * HH + k0 + kk;
                a_h[i] = sh[o]; a_l[i] = sl[o];
            }
        }
#pragma unroll
        for (int i = 0; i < BNUM; i++) {
            int flat = i * 256 + tid;
            int n = flat >> 4, kk = flat & 15;
            float x = 0.f;
            if (MODE == 2) {
                if (n < CC) x = W[(size_t)n * HH + k0 + kk];
            } else {
                x = W[(size_t)(col0 + n) * HH + k0 + kk];
            }
            tsplit(x, b_h[i], b_l[i]);
        }
    };

    auto r2s = [&](int s) {
        float* Ah = sm + s * STAGE;
        float* Al = Ah + A_ST;
        float* Bh = Al + A_ST;
        float* Bl = Bh + B_ST;
#pragma unroll
        for (int i = 0; i < ANUM; i++) {
            int flat = i * 256 + tid;
            int r = flat >> 4, kk = flat & 15;
            int mt = r >> 4, rl = r & 15, ks = kk >> 3, kl = kk & 7;
            int addr = (((mt * 2 + ks) * 32 + (rl & 7) * 4 + (kl & 3)) << 2)
                       + (rl >> 3) + ((kl >> 2) << 1);
            Ah[addr] = a_h[i]; Al[addr] = a_l[i];
        }
#pragma unroll
        for (int i = 0; i < BNUM; i++) {
            int flat = i * 256 + tid;
            int n = flat >> 4, kk = flat & 15;
            int nt = n >> 3, ks = kk >> 3, kl = kk & 7;
            int addr = (((nt * 2 + ks) * 32 + (n & 7) * 4 + (kl & 3)) << 1) + (kl >> 2);
            Bh[addr] = b_h[i]; Bl[addr] = b_l[i];
        }
    };

    g2r(0);
    r2s(0);
    __syncthreads();

    for (int ch = 0; ch < NCH; ch++) {
        const int s = ch & 1;
        if (ch + 1 < NCH) g2r(ch + 1);

        const float* Ah = sm + s * STAGE;
        const float* Al = Ah + A_ST;
        const float* Bh = Al + A_ST;
        const float* Bl = Bh + B_ST;
#pragma unroll
        for (int ks = 0; ks < 2; ks++) {
            uint4 Afh[MI], Afl[MI];
            uint2 Bfh[4], Bfl[4];
#pragma unroll
            for (int i = 0; i < MI; i++) {
                int mt = base_mt + i;
                Afh[i] = *(const uint4*)(Ah + ((mt * 2 + ks) * 32 + lane) * 4);
                Afl[i] = *(const uint4*)(Al + ((mt * 2 + ks) * 32 + lane) * 4);
            }
#pragma unroll
            for (int j = 0; j < 4; j++) {
                int nt = base_nt + j;
                Bfh[j] = *(const uint2*)(Bh + ((nt * 2 + ks) * 32 + lane) * 2);
                Bfl[j] = *(const uint2*)(Bl + ((nt * 2 + ks) * 32 + lane) * 2);
            }
#pragma unroll
            for (int i = 0; i < MI; i++)
#pragma unroll
                for (int j = 0; j < 4; j++) {
                    mma8(acc[i][j], (const uint32_t*)&Afh[i], (const uint32_t*)&Bfh[j]);
                    mma8(acc[i][j], (const uint32_t*)&Afl[i], (const uint32_t*)&Bfh[j]);
                    mma8(acc[i][j], (const uint32_t*)&Afh[i], (const uint32_t*)&Bfl[j]);
                }
        }
        if (ch + 1 < NCH) r2s(s ^ 1);
        __syncthreads();
    }

    // ---- epilogue: straight from accumulators ----
#pragma unroll
    for (int i = 0; i < MI; i++) {
        int r_base = row0 + (base_mt + i) * 16 + (lane >> 2);
#pragma unroll
        for (int j = 0; j < 4; j++) {
            int c = col0 + (base_nt + j) * 8 + 2 * (lane & 3);
#pragma unroll
            for (int h = 0; h < 2; h++) {
                int r = r_base + h * 8;
                float v0 = acc[i][j][2 * h], v1 = acc[i][j][2 * h + 1];
                if (MODE == 2) {
                    if (c < CC)
                        *(float2*)(g_P3 + (size_t)r * CC + c) = make_float2(v0, v1);
                } else {
                    size_t off = (size_t)r * HH + c;
                    float t0, t1;
                    if (MODE == 0) {
                        t0 = tanhf(v0); t1 = tanhf(v1);
                    } else {
                        float2 ph = *(const float2*)(g_P1h + off);
                        float2 pl = *(const float2*)(g_P1l + off);
                        t0 = (ph.x + pl.x) + tanhf(v0);
                        t1 = (ph.y + pl.y) + tanhf(v1);
                    }
                    float h0, l0, h1, l1;
                    tsplit(t0, h0, l0); tsplit(t1, h1, l1);
                    float* oh = (MODE == 0) ? g_P1h : g_P12h;
                    float* ol = (MODE == 0) ? g_P1l : g_P12l;
                    *(float2*)(oh + off) = make_float2(h0, h1);
                    *(float2*)(ol + off) = make_float2(l0, l1);
                }
            }
        }
    }
}

// ============================================================================
// class_inputs[b,c,h] = sum_l attn[b,l,c] * V[b,l,h]
// tf32 3-term mma: per CTA M=64 (C pad), N=128 (h), K=2048.
// ============================================================================
__global__ __launch_bounds__(256, 1) void classmm_mma(const float* __restrict__ attn,
                                                      const float* __restrict__ V,
                                                      float* __restrict__ Out) {
    constexpr int KC = 16;
    constexpr int NCH = LL / KC;          // 128
    constexpr int A_ST = 64 * KC;         // 1024
    constexpr int B_ST = 128 * KC;        // 2048
    constexpr int STAGE = 2 * A_ST + 2 * B_ST;  // 6144
    constexpr int MI = 2;
    constexpr int ANUM = A_ST / 256;      // 4
    constexpr int BNUM = B_ST / 256;      // 8

    extern __shared__ __align__(16) float sm[];

    const int tid = threadIdx.x;
    const int lane = tid & 31;
    const int warp = tid >> 5;
    const int b = blockIdx.y;
    const int h0 = blockIdx.x * 128;

    const int wm = warp >> 2;             // 0..1 (32 rows each)
    const int wn = warp & 3;              // 0..3 (32 cols each)
    const int base_mt = wm * MI;
    const int base_nt = wn * 4;

    float acc[MI][4][4] = {};
    float a_h[ANUM], a_l[ANUM], b_h[BNUM], b_l[BNUM];

    auto g2r = [&](int ch) {
        const int k0 = ch * KC;
#pragma unroll
        for (int i = 0; i < ANUM; i++) {
            int flat = i * 256 + tid;
            int m = flat & 63, kk = flat >> 6;
            float x = (m < CC) ? attn[((size_t)b * LL + k0 + kk) * CC + m] : 0.f;
            tsplit(x, a_h[i], a_l[i]);
        }
#pragma unroll
        for (int i = 0; i < BNUM; i++) {
            int flat = i * 256 + tid;
            int n = flat & 127, kk = flat >> 7;
            float x = V[((size_t)b * LL + k0 + kk) * HH + h0 + n];
            tsplit(x, b_h[i], b_l[i]);
        }
    };

    auto r2s = [&](int s) {
        float* Ah = sm + s * STAGE;
        float* Al = Ah + A_ST;
        float* Bh = Al + A_ST;
        float* Bl = Bh + B_ST;
#pragma unroll
        for (int i = 0; i < ANUM; i++) {
            int flat = i * 256 + tid;
            int m = flat & 63, kk = flat >> 6;
            int mt = m >> 4, rl = m & 15, ks = kk >> 3, kl = kk & 7;
            int addr = (((mt * 2 + ks) * 32 + (rl & 7) * 4 + (kl & 3)) << 2)
                       + (rl >> 3) + ((kl >> 2) << 1);
            Ah[addr] = a_h[i]; Al[addr] = a_l[i];
        }
#pragma unroll
        for (int i = 0; i < BNUM; i++) {
            int flat = i * 256 + tid;
            int n = flat & 127, kk = flat >> 7;
            int nt = n >> 3, ks = kk >> 3, kl = kk & 7;
            int addr = (((nt * 2 + ks) * 32 + (n & 7) * 4 + (kl & 3)) << 1) + (kl >> 2);
            Bh[addr] = b_h[i]; Bl[addr] = b_l[i];
        }
    };

    g2r(0);
    r2s(0);
    __syncthreads();

    for (int ch = 0; ch < NCH; ch++) {
        const int s = ch & 1;
        if (ch + 1 < NCH) g2r(ch + 1);

        const float* Ah = sm + s * STAGE;
        const float* Al = Ah + A_ST;
        const float* Bh = Al + A_ST;
        const float* Bl = Bh + B_ST;
#pragma unroll
        for (int ks = 0; ks < 2; ks++) {
            uint4 Afh[MI], Afl[MI];
            uint2 Bfh[4], Bfl[4];
#pragma unroll
            for (int i = 0; i < MI; i++) {
                int mt = base_mt + i;
                Afh[i] = *(const uint4*)(Ah + ((mt * 2 + ks) * 32 + lane) * 4);
                Afl[i] = *(const uint4*)(Al + ((mt * 2 + ks) * 32 + lane) * 4);
            }
#pragma unroll
            for (int j = 0; j < 4; j++) {
                int nt = base_nt + j;
                Bfh[j] = *(const uint2*)(Bh + ((nt * 2 + ks) * 32 + lane) * 2);
                Bfl[j] = *(const uint2*)(Bl + ((nt * 2 + ks) * 32 + lane) * 2);
            }
#pragma unroll
            for (int i = 0; i < MI; i++)
#pragma unroll
                for (int j = 0; j < 4; j++) {
                    mma8(acc[i][j], (const uint32_t*)&Afh[i], (const uint32_t*)&Bfh[j]);
                    mma8(acc[i][j], (const uint32_t*)&Afl[i], (const uint32_t*)&Bfh[j]);
                    mma8(acc[i][j], (const uint32_t*)&Afh[i], (const uint32_t*)&Bfl[j]);
                }
        }
        if (ch + 1 < NCH) r2s(s ^ 1);
        __syncthreads();
    }

#pragma unroll
    for (int i = 0; i < MI; i++) {
        int c_base = (base_mt + i) * 16 + (lane >> 2);
#pragma unroll
        for (int j = 0; j < 4; j++) {
            int hc = h0 + (base_nt + j) * 8 + 2 * (lane & 3);
#pragma unroll
            for (int h = 0; h < 2; h++) {
                int cls = c_base + h * 8;
                if (cls < CC)
                    *(float2*)(Out + ((size_t)b * CC + cls) * HH + hc)
                        = make_float2(acc[i][j][2 * h], acc[i][j][2 * h + 1]);
            }
        }
    }
}

// ============================================================================
// Fill-at-(len-1) + avgpool3 (count_include_pad=False) + softmax + mask.
// ============================================================================
__global__ __launch_bounds__(128) void pool_softmax_kernel(const void* __restrict__ lens_raw,
                                                           float* __restrict__ attn,
                                                           float* __restrict__ smooth) {
    const int b = blockIdx.y;
    const int l0 = blockIdx.x * 128;
    const int len = load_len(lens_raw, b);

    __shared__ float s[130][CC];
    const int tid = threadIdx.x;

    for (int i = tid; i < 130 * CC; i += 128) {
        int rr = i / CC, c = i - rr * CC;
        int l = l0 - 1 + rr;
        l = max(0, min(l, LL - 1));
        int src = min(l, len - 1);
        s[rr][c] = g_P3[((size_t)b * LL + src) * CC + c];
    }
    __syncthreads();

    const int l = l0 + tid;
    const bool hasL = (l > 0), hasR = (l < LL - 1);
    const float inv = 1.0f / (float)(1 + (hasL ? 1 : 0) + (hasR ? 1 : 0));
    const int rr = tid + 1;

    float v[CC];
    float mx = -1e30f;
#pragma unroll
    for (int c = 0; c < CC; c++) {
        float t = s[rr][c];
        if (hasL) t += s[rr - 1][c];
        if (hasR) t += s[rr + 1][c];
        t *= inv;
        v[c] = t;
        mx = fmaxf(mx, t);
    }
    const size_t base = ((size_t)b * LL + l) * CC;
    float sum = 0.f;
#pragma unroll
    for (int c = 0; c < CC; c++) {
        smooth[base + c] = v[c];
        float e = expf(v[c] - mx);
        v[c] = e;
        sum += e;
    }
    const float isum = (l < len) ? (1.0f / sum) : 0.0f;
#pragma unroll
    for (int c = 0; c < CC; c++) attn[base + c] = v[c] * isum;
}

// ============================================================================
extern "C" void kernel_launch(void* const* d_in, const int* in_sizes, int n_in,
                              void* d_out, int out_size) {
    const float* keys = (const float*)d_in[0];
    const float* vals = (const float*)d_in[1];
    const void*  lens = d_in[2];
    const float* W1 = (const float*)d_in[3];
    const float* W2 = (const float*)d_in[4];
    const float* W3 = (const float*)d_in[5];

    float* attn   = (float*)d_out;                        // (B, L, C)
    float* cls    = attn + (size_t)BB * LL * CC;          // (B, C, H)
    float* smooth = cls + (size_t)BB * CC * HH;           // (B, L, C)

    // dynamic smem: 2 stages of fragment-ordered (Ah, Al, Bh, Bl)
    const int SM12 = 2 * (2 * 128 * 16 + 2 * 128 * 16) * 4;  // 65536
    const int SM3  = 2 * (2 * 128 * 16 + 2 * 64 * 16) * 4;   // 49152
    const int SMC  = 2 * (2 * 64 * 16 + 2 * 128 * 16) * 4;   // 49152
    cudaFuncSetAttribute(gemm_mma<0>, cudaFuncAttributeMaxDynamicSharedMemorySize, SM12);
    cudaFuncSetAttribute(gemm_mma<1>, cudaFuncAttributeMaxDynamicSharedMemorySize, SM12);
    cudaFuncSetAttribute(gemm_mma<2>, cudaFuncAttributeMaxDynamicSharedMemorySize, SM3);
    cudaFuncSetAttribute(classmm_mma, cudaFuncAttributeMaxDynamicSharedMemorySize, SMC);

    gemm_mma<0><<<dim3(HH / 128, MM / 128), 256, SM12>>>(keys, W1);
    gemm_mma<1><<<dim3(HH / 128, MM / 128), 256, SM12>>>(nullptr, W2);
    gemm_mma<2><<<dim3(1, MM / 128), 256, SM3>>>(nullptr, W3);
    pool_softmax_kernel<<<dim3(LL / 128, BB), 128>>>(lens, attn, smooth);
    classmm_mma<<<dim3(HH / 128, BB), 256, SMC>>>(attn, vals, cls);
}

// round 6
// speedup vs baseline: 2.7419x; 2.2348x over previous
#include <cuda_runtime.h>
#include <cuda_fp16.h>
#include <cstdint>
#include <math.h>

#define BB 32
#define LL 2048
#define HH 512
#define CC 50
#define MM (BB * LL)   // 65536

// ---- scratch: half hi/lo planes (allocation-free) ----
__device__ __align__(16) __half g_P1h[(size_t)MM * HH];
__device__ __align__(16) __half g_P1l[(size_t)MM * HH];
__device__ __align__(16) __half g_P12h[(size_t)MM * HH];
__device__ __align__(16) __half g_P12l[(size_t)MM * HH];
__device__ __align__(16) float  g_P3[(size_t)MM * CC];

// ============================================================================
// helpers
// ============================================================================
__device__ __forceinline__ uint32_t s32(const void* p) {
    return (uint32_t)__cvta_generic_to_shared(p);
}
__device__ __forceinline__ void ldsm4(uint32_t* r, uint32_t a) {
    asm volatile("ldmatrix.sync.aligned.m8n8.x4.shared.b16 {%0,%1,%2,%3}, [%4];"
        : "=r"(r[0]), "=r"(r[1]), "=r"(r[2]), "=r"(r[3]) : "r"(a));
}
__device__ __forceinline__ void ldsm4t(uint32_t* r, uint32_t a) {
    asm volatile("ldmatrix.sync.aligned.m8n8.x4.trans.shared.b16 {%0,%1,%2,%3}, [%4];"
        : "=r"(r[0]), "=r"(r[1]), "=r"(r[2]), "=r"(r[3]) : "r"(a));
}
__device__ __forceinline__ void mma16(float* d, const uint32_t* a, const uint32_t* b) {
    asm volatile("mma.sync.aligned.m16n8k16.row.col.f32.f16.f16.f32 "
        "{%0,%1,%2,%3},{%4,%5,%6,%7},{%8,%9},{%0,%1,%2,%3};"
        : "+f"(d[0]), "+f"(d[1]), "+f"(d[2]), "+f"(d[3])
        : "r"(a[0]), "r"(a[1]), "r"(a[2]), "r"(a[3]), "r"(b[0]), "r"(b[1]));
}
__device__ __forceinline__ uint32_t packh2(float a, float b) {
    __half2 h = __floats2half2_rn(a, b);
    return *reinterpret_cast<uint32_t*>(&h);
}
__device__ __forceinline__ void hsplit(float x, float& hf, float& lf) {
    hf = __half2float(__float2half_rn(x));
    lf = x - hf;   // rounded to half at pack time
}
__device__ __forceinline__ float tanh_fast(float x) {
    float xc = fminf(fmaxf(x, -15.f), 15.f);
    float e = __expf(2.f * xc);
    return 1.f - __fdividef(2.f, e + 1.f);
}
// sent_lens may be int32 or int64. lens in [1, 2048]: for int64 LE, word[1]=0.
__device__ __forceinline__ int load_len(const void* p, int b) {
    const int* w = (const int*)p;
    bool is64 = (w[1] == 0);
    return is64 ? w[2 * b] : w[b];
}

// ============================================================================
// fp16 3-term GEMM: D(128 x NT) = A(128 x 512) * W^T
// MODE 0: A = keys (split on load), epi: split(tanh(D)) -> g_P1h/l
// MODE 1: A = g_P1 planes,          epi: split(P1 + tanh(D)) -> g_P12h/l
// MODE 2: A = g_P12 planes, NT=64, W has 50 rows, epi: D -> g_P3 (c<50)
// SMEM: A/B tiles row-major [row][k], row stride 40 halfs (ldmatrix-friendly).
// ============================================================================
template <int MODE>
__global__ __launch_bounds__(256, 1) void gemm_h(const float* __restrict__ Ag,
                                                 const float* __restrict__ W) {
    constexpr int NT = (MODE == 2) ? 64 : 128;
    constexpr int KC = 32;
    constexpr int NCH = HH / KC;             // 16
    constexpr int LDA = KC + 8;              // 40 halfs (80B rows, bank-clean)
    constexpr int A_ST = 128 * LDA;
    constexpr int B_ST = NT * LDA;
    constexpr int STAGE = 2 * A_ST + 2 * B_ST;
    constexpr int MI = (MODE == 2) ? 2 : 4;
    constexpr int BF4 = NT * KC / 4 / 256;   // 4 or 2

    extern __shared__ __align__(16) __half sm[];

    const int tid = threadIdx.x;
    const int lane = tid & 31;
    const int warp = tid >> 5;
    const int row0 = blockIdx.y * 128;
    const int col0 = blockIdx.x * NT;

    const int base_m = (MODE == 2) ? (warp >> 1) * 32 : (warp >> 2) * 64;
    const int base_n = (MODE == 2) ? (warp & 1) * 32 : (warp & 3) * 32;

    const __half* gAh = (MODE == 1) ? g_P1h : g_P12h;
    const __half* gAl = (MODE == 1) ? g_P1l : g_P12l;

    float acc[MI][4][4] = {};
    float4 aA[4]; uint4 aPh[2], aPl[2]; float4 aB[BF4];

    auto g2r = [&](int ch) {
        const int k0 = ch * KC;
        if constexpr (MODE == 0) {
#pragma unroll
            for (int i = 0; i < 4; i++) {
                int f = i * 256 + tid, r = f >> 3, kc = f & 7;
                aA[i] = *(const float4*)(Ag + (size_t)(row0 + r) * HH + k0 + kc * 4);
            }
        } else {
#pragma unroll
            for (int i = 0; i < 2; i++) {
                int u = i * 256 + tid, r = u >> 2, kc8 = u & 3;
                size_t off = (size_t)(row0 + r) * HH + k0 + kc8 * 8;
                aPh[i] = *(const uint4*)(gAh + off);
                aPl[i] = *(const uint4*)(gAl + off);
            }
        }
#pragma unroll
        for (int i = 0; i < BF4; i++) {
            int f = i * 256 + tid, n = f >> 3, kc = f & 7;
            float4 x = make_float4(0.f, 0.f, 0.f, 0.f);
            if (MODE != 2 || n < CC)
                x = *(const float4*)(W + (size_t)(MODE == 2 ? n : col0 + n) * HH + k0 + kc * 4);
            aB[i] = x;
        }
    };

    auto r2s = [&](int s) {
        __half* Ah = sm + s * STAGE;
        __half* Al = Ah + A_ST;
        __half* Bh = Al + A_ST;
        __half* Bl = Bh + B_ST;
        if constexpr (MODE == 0) {
#pragma unroll
            for (int i = 0; i < 4; i++) {
                int f = i * 256 + tid, r = f >> 3, kc = f & 7;
                float h0, l0, h1, l1, h2, l2, h3, l3;
                hsplit(aA[i].x, h0, l0); hsplit(aA[i].y, h1, l1);
                hsplit(aA[i].z, h2, l2); hsplit(aA[i].w, h3, l3);
                *(uint2*)(Ah + r * LDA + kc * 4) = make_uint2(packh2(h0, h1), packh2(h2, h3));
                *(uint2*)(Al + r * LDA + kc * 4) = make_uint2(packh2(l0, l1), packh2(l2, l3));
            }
        } else {
#pragma unroll
            for (int i = 0; i < 2; i++) {
                int u = i * 256 + tid, r = u >> 2, kc8 = u & 3;
                *(uint4*)(Ah + r * LDA + kc8 * 8) = aPh[i];
                *(uint4*)(Al + r * LDA + kc8 * 8) = aPl[i];
            }
        }
#pragma unroll
        for (int i = 0; i < BF4; i++) {
            int f = i * 256 + tid, n = f >> 3, kc = f & 7;
            float h0, l0, h1, l1, h2, l2, h3, l3;
            hsplit(aB[i].x, h0, l0); hsplit(aB[i].y, h1, l1);
            hsplit(aB[i].z, h2, l2); hsplit(aB[i].w, h3, l3);
            *(uint2*)(Bh + n * LDA + kc * 4) = make_uint2(packh2(h0, h1), packh2(h2, h3));
            *(uint2*)(Bl + n * LDA + kc * 4) = make_uint2(packh2(l0, l1), packh2(l2, l3));
        }
    };

    auto compute = [&](int s) {
        const __half* Ah = sm + s * STAGE;
        const __half* Al = Ah + A_ST;
        const __half* Bh = Al + A_ST;
        const __half* Bl = Bh + B_ST;
#pragma unroll
        for (int ks = 0; ks < 2; ks++) {
            uint32_t fAh[MI][4], fAl[MI][4], fBh[4][2], fBl[4][2];
#pragma unroll
            for (int mi = 0; mi < MI; mi++) {
                int row = base_m + mi * 16 + (lane & 15);
                int off = row * LDA + ks * 16 + ((lane >> 4) << 3);
                ldsm4(fAh[mi], s32(Ah + off));
                ldsm4(fAl[mi], s32(Al + off));
            }
#pragma unroll
            for (int p = 0; p < 2; p++) {
                int n = base_n + p * 16 + (lane & 7) + ((lane >> 4) << 3);
                int off = n * LDA + ks * 16 + (((lane >> 3) & 1) << 3);
                uint32_t r[4];
                ldsm4(r, s32(Bh + off));
                fBh[2 * p][0] = r[0]; fBh[2 * p][1] = r[1];
                fBh[2 * p + 1][0] = r[2]; fBh[2 * p + 1][1] = r[3];
                ldsm4(r, s32(Bl + off));
                fBl[2 * p][0] = r[0]; fBl[2 * p][1] = r[1];
                fBl[2 * p + 1][0] = r[2]; fBl[2 * p + 1][1] = r[3];
            }
#pragma unroll
            for (int mi = 0; mi < MI; mi++)
#pragma unroll
                for (int j = 0; j < 4; j++) {
                    mma16(acc[mi][j], fAh[mi], fBh[j]);
                    mma16(acc[mi][j], fAl[mi], fBh[j]);
                    mma16(acc[mi][j], fAh[mi], fBl[j]);
                }
        }
    };

    g2r(0); r2s(0); __syncthreads();
    for (int ch = 0; ch < NCH; ch++) {
        const int s = ch & 1;
        if (ch + 1 < NCH) g2r(ch + 1);
        compute(s);
        if (ch + 1 < NCH) r2s(s ^ 1);
        __syncthreads();
    }

    // ---- epilogue ----
#pragma unroll
    for (int mi = 0; mi < MI; mi++)
#pragma unroll
        for (int j = 0; j < 4; j++)
#pragma unroll
            for (int hh = 0; hh < 2; hh++) {
                int r = row0 + base_m + mi * 16 + (lane >> 2) + hh * 8;
                int c = col0 + base_n + j * 8 + 2 * (lane & 3);
                float v0 = acc[mi][j][2 * hh], v1 = acc[mi][j][2 * hh + 1];
                if constexpr (MODE == 2) {
                    if (c < CC)
                        *(float2*)(g_P3 + (size_t)r * CC + c) = make_float2(v0, v1);
                } else {
                    size_t off = (size_t)r * HH + c;
                    float t0, t1;
                    if constexpr (MODE == 0) {
                        t0 = tanh_fast(v0); t1 = tanh_fast(v1);
                    } else {
                        float2 pf = __half22float2(*(const __half2*)(g_P1h + off));
                        float2 qf = __half22float2(*(const __half2*)(g_P1l + off));
                        t0 = (pf.x + qf.x) + tanh_fast(v0);
                        t1 = (pf.y + qf.y) + tanh_fast(v1);
                    }
                    float h0, l0, h1, l1;
                    hsplit(t0, h0, l0); hsplit(t1, h1, l1);
                    __half* oh = (MODE == 0) ? g_P1h : g_P12h;
                    __half* ol = (MODE == 0) ? g_P1l : g_P12l;
                    *(uint32_t*)(oh + off) = packh2(h0, h1);
                    *(uint32_t*)(ol + off) = packh2(l0, l1);
                }
            }
}

// ============================================================================
// class_inputs[b,c,h] = sum_l attn[b,l,c] * V[b,l,h]   (fp16 3-term, trans ldsm)
// CTA: one batch, M=64 (c pad), N=128 (h), K=2048, KC=32.
// SMEM natural [k][m] / [k][n]; fragments via ldmatrix.trans.
// ============================================================================
__global__ __launch_bounds__(256, 1) void classmm_h(const float* __restrict__ attn,
                                                    const float* __restrict__ V,
                                                    float* __restrict__ Out) {
    constexpr int KC = 32;
    constexpr int NCH = LL / KC;    // 64
    constexpr int LDAA = 72;        // [k][m] row stride (144B, bank-clean)
    constexpr int LDB = 136;        // [k][n] row stride (272B, bank-clean)
    constexpr int A_ST = KC * LDAA;
    constexpr int B_ST = KC * LDB;
    constexpr int STAGE = 2 * A_ST + 2 * B_ST;
    constexpr int MI = 2;

    extern __shared__ __align__(16) __half sm[];
    const int tid = threadIdx.x, lane = tid & 31, warp = tid >> 5;
    const int b = blockIdx.y;
    const int h0 = blockIdx.x * 128;
    const int base_m = (warp >> 2) * 32;
    const int base_n = (warp & 3) * 32;

    float acc[MI][4][4] = {};
    float2 aA[4]; float4 aB[4];
    const int m2 = tid & 31;     // m = m2*2
    const int kkA = tid >> 5;    // 0..7

    auto g2r = [&](int ch) {
        const int k0 = ch * KC;
#pragma unroll
        for (int i = 0; i < 4; i++) {
            int kk = kkA + i * 8;
            float2 x = make_float2(0.f, 0.f);
            if (m2 < 25) x = *(const float2*)(attn + ((size_t)b * LL + k0 + kk) * CC + m2 * 2);
            aA[i] = x;
        }
#pragma unroll
        for (int i = 0; i < 4; i++) {
            int f = i * 256 + tid, n4 = f & 31, kk = f >> 5;
            aB[i] = *(const float4*)(V + ((size_t)b * LL + k0 + kk) * HH + h0 + n4 * 4);
        }
    };
    auto r2s = [&](int s) {
        __half* Ah = sm + s * STAGE;
        __half* Al = Ah + A_ST;
        __half* Bh = Al + A_ST;
        __half* Bl = Bh + B_ST;
#pragma unroll
        for (int i = 0; i < 4; i++) {
            int kk = kkA + i * 8;
            float h0_, l0_, h1_, l1_;
            hsplit(aA[i].x, h0_, l0_); hsplit(aA[i].y, h1_, l1_);
            *(uint32_t*)(Ah + kk * LDAA + m2 * 2) = packh2(h0_, h1_);
            *(uint32_t*)(Al + kk * LDAA + m2 * 2) = packh2(l0_, l1_);
        }
#pragma unroll
        for (int i = 0; i < 4; i++) {
            int f = i * 256 + tid, n4 = f & 31, kk = f >> 5;
            float h0_, l0_, h1_, l1_, h2_, l2_, h3_, l3_;
            hsplit(aB[i].x, h0_, l0_); hsplit(aB[i].y, h1_, l1_);
            hsplit(aB[i].z, h2_, l2_); hsplit(aB[i].w, h3_, l3_);
            *(uint2*)(Bh + kk * LDB + n4 * 4) = make_uint2(packh2(h0_, h1_), packh2(h2_, h3_));
            *(uint2*)(Bl + kk * LDB + n4 * 4) = make_uint2(packh2(l0_, l1_), packh2(l2_, l3_));
        }
    };
    auto compute = [&](int s) {
        const __half* Ah = sm + s * STAGE;
        const __half* Al = Ah + A_ST;
        const __half* Bh = Al + A_ST;
        const __half* Bl = Bh + B_ST;
#pragma unroll
        for (int ks = 0; ks < 2; ks++) {
            uint32_t fAh[MI][4], fAl[MI][4], fBh[4][2], fBl[4][2];
#pragma unroll
            for (int mi = 0; mi < MI; mi++) {
                int krow = ks * 16 + (lane & 7) + ((lane >> 4) << 3);
                int moff = base_m + mi * 16 + ((lane >> 3) & 1) * 8;
                int off = krow * LDAA + moff;
                ldsm4t(fAh[mi], s32(Ah + off));
                ldsm4t(fAl[mi], s32(Al + off));
            }
#pragma unroll
            for (int p = 0; p < 2; p++) {
                int krow = ks * 16 + (lane & 7) + (((lane >> 3) & 1) << 3);
                int noff = base_n + p * 16 + ((lane >> 4) << 3);
                int off = krow * LDB + noff;
                uint32_t r[4];
                ldsm4t(r, s32(Bh + off));
                fBh[2 * p][0] = r[0]; fBh[2 * p][1] = r[1];
                fBh[2 * p + 1][0] = r[2]; fBh[2 * p + 1][1] = r[3];
                ldsm4t(r, s32(Bl + off));
                fBl[2 * p][0] = r[0]; fBl[2 * p][1] = r[1];
                fBl[2 * p + 1][0] = r[2]; fBl[2 * p + 1][1] = r[3];
            }
#pragma unroll
            for (int mi = 0; mi < MI; mi++)
#pragma unroll
                for (int j = 0; j < 4; j++) {
                    mma16(acc[mi][j], fAh[mi], fBh[j]);
                    mma16(acc[mi][j], fAl[mi], fBh[j]);
                    mma16(acc[mi][j], fAh[mi], fBl[j]);
                }
        }
    };

    g2r(0); r2s(0); __syncthreads();
    for (int ch = 0; ch < NCH; ch++) {
        const int s = ch & 1;
        if (ch + 1 < NCH) g2r(ch + 1);
        compute(s);
        if (ch + 1 < NCH) r2s(s ^ 1);
        __syncthreads();
    }

#pragma unroll
    for (int mi = 0; mi < MI; mi++)
#pragma unroll
        for (int j = 0; j < 4; j++)
#pragma unroll
            for (int hh = 0; hh < 2; hh++) {
                int c = base_m + mi * 16 + (lane >> 2) + hh * 8;
                int h = h0 + base_n + j * 8 + 2 * (lane & 3);
                if (c < CC)
                    *(float2*)(Out + ((size_t)b * CC + c) * HH + h)
                        = make_float2(acc[mi][j][2 * hh], acc[mi][j][2 * hh + 1]);
            }
}

// ============================================================================
// Fill-at-(len-1) + avgpool3 (count_include_pad=False) + softmax + mask.
// ============================================================================
__global__ __launch_bounds__(128) void pool_softmax_kernel(const void* __restrict__ lens_raw,
                                                           float* __restrict__ attn,
                                                           float* __restrict__ smooth) {
    const int b = blockIdx.y;
    const int l0 = blockIdx.x * 128;
    const int len = load_len(lens_raw, b);

    __shared__ float s[130][CC];
    const int tid = threadIdx.x;

    for (int i = tid; i < 130 * CC; i += 128) {
        int rr = i / CC, c = i - rr * CC;
        int l = l0 - 1 + rr;
        l = max(0, min(l, LL - 1));
        int src = min(l, len - 1);
        s[rr][c] = g_P3[((size_t)b * LL + src) * CC + c];
    }
    __syncthreads();

    const int l = l0 + tid;
    const bool hasL = (l > 0), hasR = (l < LL - 1);
    const float inv = 1.0f / (float)(1 + (hasL ? 1 : 0) + (hasR ? 1 : 0));
    const int rr = tid + 1;

    float v[CC];
    float mx = -1e30f;
#pragma unroll
    for (int c = 0; c < CC; c++) {
        float t = s[rr][c];
        if (hasL) t += s[rr - 1][c];
        if (hasR) t += s[rr + 1][c];
        t *= inv;
        v[c] = t;
        mx = fmaxf(mx, t);
    }
    const size_t base = ((size_t)b * LL + l) * CC;
    float sum = 0.f;
#pragma unroll
    for (int c = 0; c < CC; c++) {
        smooth[base + c] = v[c];
        float e = expf(v[c] - mx);
        v[c] = e;
        sum += e;
    }
    const float isum = (l < len) ? (1.0f / sum) : 0.0f;
#pragma unroll
    for (int c = 0; c < CC; c++) attn[base + c] = v[c] * isum;
}

// ============================================================================
extern "C" void kernel_launch(void* const* d_in, const int* in_sizes, int n_in,
                              void* d_out, int out_size) {
    const float* keys = (const float*)d_in[0];
    const float* vals = (const float*)d_in[1];
    const void*  lens = d_in[2];
    const float* W1 = (const float*)d_in[3];
    const float* W2 = (const float*)d_in[4];
    const float* W3 = (const float*)d_in[5];

    float* attn   = (float*)d_out;                        // (B, L, C)
    float* cls    = attn + (size_t)BB * LL * CC;          // (B, C, H)
    float* smooth = cls + (size_t)BB * CC * HH;           // (B, L, C)

    const int SM12 = 2 * (2 * 128 * 40 + 2 * 128 * 40) * 2;  // 81920 B
    const int SM3  = 2 * (2 * 128 * 40 + 2 * 64 * 40) * 2;   // 61440 B
    const int SMC  = 2 * (2 * 32 * 72 + 2 * 32 * 136) * 2;   // 53248 B
    cudaFuncSetAttribute(gemm_h<0>, cudaFuncAttributeMaxDynamicSharedMemorySize, SM12);
    cudaFuncSetAttribute(gemm_h<1>, cudaFuncAttributeMaxDynamicSharedMemorySize, SM12);
    cudaFuncSetAttribute(gemm_h<2>, cudaFuncAttributeMaxDynamicSharedMemorySize, SM3);
    cudaFuncSetAttribute(classmm_h, cudaFuncAttributeMaxDynamicSharedMemorySize, SMC);

    gemm_h<0><<<dim3(HH / 128, MM / 128), 256, SM12>>>(keys, W1);
    gemm_h<1><<<dim3(HH / 128, MM / 128), 256, SM12>>>(nullptr, W2);
    gemm_h<2><<<dim3(1, MM / 128), 256, SM3>>>(nullptr, W3);
    pool_softmax_kernel<<<dim3(LL / 128, BB), 128>>>(lens, attn, smooth);
    classmm_h<<<dim3(HH / 128, BB), 256, SMC>>>(attn, vals, cls);
}